// round 2
// baseline (speedup 1.0000x reference)
#include <cuda_runtime.h>
#include <cuda_bf16.h>
#include <math.h>

#define N_NODES 200000
#define N_EDGES 1250000
#define D 64
#define G 128

// ---------------- device scratch (static; no allocation) ----------------
__device__ int   g_is64;                // 1 if edge_index/batch are int64
__device__ int   g_cnt[N_NODES];        // histogram, then write-cursor
__device__ int   g_rowptr[N_NODES + 1];
__device__ int   g_scan[N_NODES];
__device__ int   g_bsum[256];
__device__ int   g_bsumx[256];
__device__ int   g_esrc[N_EDGES];
__device__ float g_z[N_NODES * D];
__device__ float g_h[N_NODES * D];
__device__ float g_pool[G * 2 * D];
__device__ int   g_gb[G + 1];

// ---------------- dtype detection ----------------
// int64 little-endian values < 2^31 have zero odd 32-bit words.
__global__ void k_detect(const int* __restrict__ e) {
    if (threadIdx.x == 0 && blockIdx.x == 0) {
        int all0 = 1;
        #pragma unroll 1
        for (int i = 0; i < 64; i++)
            if (e[2 * i + 1] != 0) { all0 = 0; break; }
        g_is64 = all0;
    }
}

__device__ __forceinline__ int load_idx(const void* p, int i) {
    if (g_is64) return (int)((const long long*)p)[i];
    return ((const int*)p)[i];
}

// ---------------- CSR build ----------------
__global__ void k_zero_cnt() {
    int i = blockIdx.x * blockDim.x + threadIdx.x;
    if (i < N_NODES) g_cnt[i] = 0;
}

__global__ void k_count(const void* __restrict__ eidx) {
    int e = blockIdx.x * blockDim.x + threadIdx.x;
    if (e < N_EDGES) {
        int d = load_idx(eidx, N_EDGES + e);
        atomicAdd(&g_cnt[d], 1);
    }
}

__global__ void k_scanA() {
    __shared__ int sh[1024];
    int b = blockIdx.x, t = threadIdx.x;
    int i = b * 1024 + t;
    int v = (i < N_NODES) ? g_cnt[i] : 0;
    sh[t] = v;
    __syncthreads();
    #pragma unroll
    for (int o = 1; o < 1024; o <<= 1) {
        int u = (t >= o) ? sh[t - o] : 0;
        __syncthreads();
        sh[t] += u;
        __syncthreads();
    }
    if (i < N_NODES) g_scan[i] = sh[t] - v;   // exclusive within block
    if (t == 1023) g_bsum[b] = sh[1023];
}

__global__ void k_scanB(int nb) {
    if (threadIdx.x == 0 && blockIdx.x == 0) {
        int run = 0;
        for (int j = 0; j < nb; j++) { int c = g_bsum[j]; g_bsumx[j] = run; run += c; }
        g_rowptr[N_NODES] = run;
    }
}

__global__ void k_scanC() {
    int i = blockIdx.x * blockDim.x + threadIdx.x;
    if (i < N_NODES) {
        int v = g_scan[i] + g_bsumx[i >> 10];
        g_rowptr[i] = v;
        g_cnt[i] = v;   // write cursor
    }
}

__global__ void k_scatter(const void* __restrict__ eidx) {
    int e = blockIdx.x * blockDim.x + threadIdx.x;
    if (e < N_EDGES) {
        int dst = load_idx(eidx, N_EDGES + e);
        int src = load_idx(eidx, e);
        int pos = atomicAdd(&g_cnt[dst], 1);
        g_esrc[pos] = src;
    }
}

// ---------------- aggregation: z[i] = x[i] + sum_{j->i} x[j] ----------------
__global__ void __launch_bounds__(256) k_agg(const float* __restrict__ xin,
                                             float* __restrict__ zout) {
    int warp = (blockIdx.x * blockDim.x + threadIdx.x) >> 5;
    int lane = threadIdx.x & 31;
    if (warp >= N_NODES) return;
    const float2* __restrict__ x2 = (const float2*)xin;
    float2 a = x2[warp * 32 + lane];
    int beg = g_rowptr[warp], end = g_rowptr[warp + 1];
    for (int e = beg; e < end; e++) {
        int s = g_esrc[e];
        float2 v = __ldg(&x2[s * 32 + lane]);
        a.x += v.x; a.y += v.y;
    }
    ((float2*)zout)[warp * 32 + lane] = a;
}

// ---------------- node MLP: h = [relu] ( relu(z@w1+b1) @ w2 + b2 ) ----------------
template <bool RELU_OUT>
__global__ void __launch_bounds__(256) k_mlp(const float* __restrict__ zin,
                                             float* __restrict__ hout,
                                             const float* __restrict__ w1,
                                             const float* __restrict__ b1,
                                             const float* __restrict__ w2,
                                             const float* __restrict__ b2) {
    __shared__ float2 w1s[64][32];
    __shared__ float2 w2s[64][32];
    __shared__ float b1s[64], b2s[64];
    int t = threadIdx.x;
    for (int idx = t; idx < 64 * 32; idx += blockDim.x) {
        int k = idx >> 5, l = idx & 31;
        w1s[k][l] = make_float2(w1[k * 64 + l], w1[k * 64 + 32 + l]);
        w2s[k][l] = make_float2(w2[k * 64 + l], w2[k * 64 + 32 + l]);
    }
    if (t < 64) { b1s[t] = b1[t]; b2s[t] = b2[t]; }
    __syncthreads();

    int lane = t & 31;
    int gw = (blockIdx.x * blockDim.x + t) >> 5;
    int nw = (gridDim.x * blockDim.x) >> 5;
    for (int node = gw; node < N_NODES; node += nw) {
        float zlo = zin[node * 64 + lane];
        float zhi = zin[node * 64 + 32 + lane];
        float a0 = b1s[lane], a1 = b1s[lane + 32];
        #pragma unroll
        for (int k = 0; k < 32; k++) {
            float zk = __shfl_sync(0xffffffffu, zlo, k);
            float2 w = w1s[k][lane];
            a0 = fmaf(zk, w.x, a0); a1 = fmaf(zk, w.y, a1);
        }
        #pragma unroll
        for (int k = 0; k < 32; k++) {
            float zk = __shfl_sync(0xffffffffu, zhi, k);
            float2 w = w1s[k + 32][lane];
            a0 = fmaf(zk, w.x, a0); a1 = fmaf(zk, w.y, a1);
        }
        float t0 = fmaxf(a0, 0.f), t1 = fmaxf(a1, 0.f);
        float c0 = b2s[lane], c1 = b2s[lane + 32];
        #pragma unroll
        for (int k = 0; k < 32; k++) {
            float tk = __shfl_sync(0xffffffffu, t0, k);
            float2 w = w2s[k][lane];
            c0 = fmaf(tk, w.x, c0); c1 = fmaf(tk, w.y, c1);
        }
        #pragma unroll
        for (int k = 0; k < 32; k++) {
            float tk = __shfl_sync(0xffffffffu, t1, k);
            float2 w = w2s[k + 32][lane];
            c0 = fmaf(tk, w.x, c0); c1 = fmaf(tk, w.y, c1);
        }
        if (RELU_OUT) { c0 = fmaxf(c0, 0.f); c1 = fmaxf(c1, 0.f); }
        hout[node * 64 + lane]      = c0;
        hout[node * 64 + 32 + lane] = c1;
    }
}

// ---------------- graph segment boundaries (batch is sorted) ----------------
__global__ void k_gb(const void* __restrict__ batch) {
    int g = blockIdx.x * blockDim.x + threadIdx.x;
    if (g > G) return;
    int lo = 0, hi = N_NODES;
    while (lo < hi) {
        int mid = (lo + hi) >> 1;
        int bv = load_idx(batch, mid);
        if (bv < g) lo = mid + 1; else hi = mid;
    }
    g_gb[g] = lo;
}

// ---------------- pooling: per-graph sum & max over HID dims ----------------
__global__ void __launch_bounds__(256) k_pool(const float* __restrict__ h) {
    __shared__ float ssum[4][64], smax[4][64];
    int g = blockIdx.x, t = threadIdx.x;
    int col = t & 63, ch = t >> 6;
    int beg = g_gb[g], end = g_gb[g + 1];
    float s = 0.f, m = -INFINITY;
    for (int i = beg + ch; i < end; i += 4) {
        float v = h[i * 64 + col];
        s += v; m = fmaxf(m, v);
    }
    ssum[ch][col] = s; smax[ch][col] = m;
    __syncthreads();
    if (t < 64) {
        float S = ssum[0][t] + ssum[1][t] + ssum[2][t] + ssum[3][t];
        float M = fmaxf(fmaxf(smax[0][t], smax[1][t]), fmaxf(smax[2][t], smax[3][t]));
        g_pool[g * 128 + t]      = S;
        g_pool[g * 128 + 64 + t] = M;
    }
}

// ---------------- head MLP: 128 -> 128 -> 64 -> 32 -> 16 -> 1, SiLU ----------------
__device__ __forceinline__ float silu(float x) { return x / (1.f + expf(-x)); }

__global__ void __launch_bounds__(128) k_head(float* __restrict__ out,
        const float* __restrict__ w0, const float* __restrict__ b0,
        const float* __restrict__ w1, const float* __restrict__ b1,
        const float* __restrict__ w2, const float* __restrict__ b2,
        const float* __restrict__ w3, const float* __restrict__ b3,
        const float* __restrict__ w4, const float* __restrict__ b4) {
    __shared__ float bufA[128], bufB[128];
    int g = blockIdx.x, t = threadIdx.x;
    bufA[t] = g_pool[g * 128 + t];
    __syncthreads();
    // layer 0: 128 -> 128
    {
        float a = b0[t];
        #pragma unroll 8
        for (int k = 0; k < 128; k++) a = fmaf(bufA[k], w0[k * 128 + t], a);
        bufB[t] = silu(a);
    }
    __syncthreads();
    // layer 1: 128 -> 64
    if (t < 64) {
        float a = b1[t];
        #pragma unroll 8
        for (int k = 0; k < 128; k++) a = fmaf(bufB[k], w1[k * 64 + t], a);
        bufA[t] = silu(a);
    }
    __syncthreads();
    // layer 2: 64 -> 32
    if (t < 32) {
        float a = b2[t];
        #pragma unroll 8
        for (int k = 0; k < 64; k++) a = fmaf(bufA[k], w2[k * 32 + t], a);
        bufB[t] = silu(a);
    }
    __syncthreads();
    // layer 3: 32 -> 16
    if (t < 16) {
        float a = b3[t];
        #pragma unroll
        for (int k = 0; k < 32; k++) a = fmaf(bufB[k], w3[k * 16 + t], a);
        bufA[t] = silu(a);
    }
    __syncthreads();
    // layer 4: 16 -> 1
    if (t == 0) {
        float a = b4[0];
        #pragma unroll
        for (int k = 0; k < 16; k++) a = fmaf(bufA[k], w4[k], a);
        out[g] = a;
    }
}

// ---------------- launch ----------------
extern "C" void kernel_launch(void* const* d_in, const int* in_sizes, int n_in,
                              void* d_out, int out_size) {
    const float* x     = (const float*)d_in[0];
    const void*  eidx  = d_in[1];
    const void*  batch = d_in[2];
    const float* c1w1 = (const float*)d_in[3];
    const float* c1b1 = (const float*)d_in[4];
    const float* c1w2 = (const float*)d_in[5];
    const float* c1b2 = (const float*)d_in[6];
    const float* c2w1 = (const float*)d_in[7];
    const float* c2b1 = (const float*)d_in[8];
    const float* c2w2 = (const float*)d_in[9];
    const float* c2b2 = (const float*)d_in[10];
    const float* hw0 = (const float*)d_in[11];
    const float* hb0 = (const float*)d_in[12];
    const float* hw1 = (const float*)d_in[13];
    const float* hb1 = (const float*)d_in[14];
    const float* hw2 = (const float*)d_in[15];
    const float* hb2 = (const float*)d_in[16];
    const float* hw3 = (const float*)d_in[17];
    const float* hb3 = (const float*)d_in[18];
    const float* hw4 = (const float*)d_in[19];
    const float* hb4 = (const float*)d_in[20];
    float* out = (float*)d_out;

    void *pz, *ph;
    cudaGetSymbolAddress(&pz, g_z);
    cudaGetSymbolAddress(&ph, g_h);
    float* zbuf = (float*)pz;
    float* hbuf = (float*)ph;

    const int NB = (N_NODES + 1023) / 1024;   // 196

    // dtype detection, then CSR build
    k_detect<<<1, 32>>>((const int*)eidx);
    k_zero_cnt<<<(N_NODES + 255) / 256, 256>>>();
    k_count<<<(N_EDGES + 255) / 256, 256>>>(eidx);
    k_scanA<<<NB, 1024>>>();
    k_scanB<<<1, 1>>>(NB);
    k_scanC<<<(N_NODES + 255) / 256, 256>>>();
    k_scatter<<<(N_EDGES + 255) / 256, 256>>>(eidx);

    // graph boundaries (independent of convs)
    k_gb<<<1, 256>>>(batch);

    const int aggBlocks = (N_NODES * 32 + 255) / 256;
    const int mlpBlocks = 2048;

    // conv1 (+ inter-layer relu fused)
    k_agg<<<aggBlocks, 256>>>(x, zbuf);
    k_mlp<true><<<mlpBlocks, 256>>>(zbuf, hbuf, c1w1, c1b1, c1w2, c1b2);
    // conv2 (no trailing relu)
    k_agg<<<aggBlocks, 256>>>(hbuf, zbuf);
    k_mlp<false><<<mlpBlocks, 256>>>(zbuf, hbuf, c2w1, c2b1, c2w2, c2b2);

    // pooling + head
    k_pool<<<G, 256>>>(hbuf);
    k_head<<<G, 128>>>(out, hw0, hb0, hw1, hb1, hw2, hb2, hw3, hb3, hw4, hb4);
}

// round 3
// speedup vs baseline: 1.6130x; 1.6130x over previous
#include <cuda_runtime.h>
#include <cuda_bf16.h>
#include <math.h>

#define N_NODES 200000
#define N_EDGES 1250000
#define D 64
#define G 128

// ---------------- device scratch (static; no allocation) ----------------
__device__ int   g_is64;                // 1 if edge_index/batch are int64
__device__ int   g_cnt[N_NODES];        // histogram, then write-cursor
__device__ int   g_rowptr[N_NODES + 1];
__device__ int   g_scan[N_NODES];
__device__ int   g_bsum[256];
__device__ int   g_bsumx[256];
__device__ int   g_esrc[N_EDGES];
__device__ float g_z[N_NODES * D];
__device__ float g_h[N_NODES * D];
__device__ float g_pool[G * 2 * D];
__device__ int   g_gb[G + 1];

// ---------------- packed f32x2 helpers ----------------
__device__ __forceinline__ unsigned long long f32x2_dup(float x) {
    unsigned long long r;
    asm("mov.b64 %0, {%1, %1};" : "=l"(r) : "f"(x));
    return r;
}
__device__ __forceinline__ void f32x2_fma(unsigned long long& d,
                                          unsigned long long a,
                                          unsigned long long b) {
    asm("fma.rn.f32x2 %0, %1, %2, %0;" : "+l"(d) : "l"(a), "l"(b));
}
__device__ __forceinline__ float2 f32x2_unpack(unsigned long long a) {
    float lo, hi;
    asm("mov.b64 {%0, %1}, %2;" : "=f"(lo), "=f"(hi) : "l"(a));
    return make_float2(lo, hi);
}

// ---------------- dtype detection ----------------
// int64 little-endian values < 2^31 have zero odd 32-bit words.
__global__ void k_detect(const int* __restrict__ e) {
    if (threadIdx.x == 0 && blockIdx.x == 0) {
        int all0 = 1;
        #pragma unroll 1
        for (int i = 0; i < 64; i++)
            if (e[2 * i + 1] != 0) { all0 = 0; break; }
        g_is64 = all0;
    }
}

__device__ __forceinline__ int load_idx(const void* p, int i) {
    if (g_is64) return (int)((const long long*)p)[i];
    return ((const int*)p)[i];
}

// ---------------- CSR build ----------------
__global__ void k_zero_cnt() {
    int i = blockIdx.x * blockDim.x + threadIdx.x;
    if (i < N_NODES) g_cnt[i] = 0;
}

__global__ void k_count(const void* __restrict__ eidx) {
    int e = blockIdx.x * blockDim.x + threadIdx.x;
    if (e < N_EDGES) {
        int d = load_idx(eidx, N_EDGES + e);
        atomicAdd(&g_cnt[d], 1);
    }
}

__global__ void k_scanA() {
    __shared__ int sh[1024];
    int b = blockIdx.x, t = threadIdx.x;
    int i = b * 1024 + t;
    int v = (i < N_NODES) ? g_cnt[i] : 0;
    sh[t] = v;
    __syncthreads();
    #pragma unroll
    for (int o = 1; o < 1024; o <<= 1) {
        int u = (t >= o) ? sh[t - o] : 0;
        __syncthreads();
        sh[t] += u;
        __syncthreads();
    }
    if (i < N_NODES) g_scan[i] = sh[t] - v;   // exclusive within block
    if (t == 1023) g_bsum[b] = sh[1023];
}

// parallel scan of <=256 block sums in one block
__global__ void k_scanB(int nb) {
    __shared__ int sh[256];
    int t = threadIdx.x;
    int v = (t < nb) ? g_bsum[t] : 0;
    sh[t] = v;
    __syncthreads();
    #pragma unroll
    for (int o = 1; o < 256; o <<= 1) {
        int u = (t >= o) ? sh[t - o] : 0;
        __syncthreads();
        sh[t] += u;
        __syncthreads();
    }
    if (t < nb) g_bsumx[t] = sh[t] - v;
    if (t == nb - 1) g_rowptr[N_NODES] = sh[t];
}

__global__ void k_scanC() {
    int i = blockIdx.x * blockDim.x + threadIdx.x;
    if (i < N_NODES) {
        int v = g_scan[i] + g_bsumx[i >> 10];
        g_rowptr[i] = v;
        g_cnt[i] = v;   // write cursor
    }
}

__global__ void k_scatter(const void* __restrict__ eidx) {
    int e = blockIdx.x * blockDim.x + threadIdx.x;
    if (e < N_EDGES) {
        int dst = load_idx(eidx, N_EDGES + e);
        int src = load_idx(eidx, e);
        int pos = atomicAdd(&g_cnt[dst], 1);
        g_esrc[pos] = src;
    }
}

// ---------------- aggregation: z[i] = x[i] + sum_{j->i} x[j] ----------------
__global__ void __launch_bounds__(256) k_agg(const float* __restrict__ xin,
                                             float* __restrict__ zout) {
    int warp = (blockIdx.x * blockDim.x + threadIdx.x) >> 5;
    int lane = threadIdx.x & 31;
    if (warp >= N_NODES) return;
    const float2* __restrict__ x2 = (const float2*)xin;
    float2 a = x2[warp * 32 + lane];
    int beg = g_rowptr[warp], end = g_rowptr[warp + 1];
    for (int e = beg; e < end; e++) {
        int s = g_esrc[e];
        float2 v = __ldg(&x2[s * 32 + lane]);
        a.x += v.x; a.y += v.y;
    }
    ((float2*)zout)[warp * 32 + lane] = a;
}

// ---------------- node MLP (thread-per-node, packed f32x2 FMA) ----------------
// h = [relu]( relu(z@w1+b1) @ w2 + b2 )
template <bool RELU_OUT>
__global__ void __launch_bounds__(128) k_mlp(const float* __restrict__ zin,
                                             float* __restrict__ hout,
                                             const float* __restrict__ w1,
                                             const float* __restrict__ b1,
                                             const float* __restrict__ w2,
                                             const float* __restrict__ b2) {
    __shared__ float w1s[64 * 64];
    __shared__ float w2s[64 * 64];
    __shared__ float b1s[64], b2s[64];
    int t = threadIdx.x;
    #pragma unroll
    for (int i = t; i < 64 * 64; i += 128) { w1s[i] = w1[i]; w2s[i] = w2[i]; }
    if (t < 64) { b1s[t] = b1[t]; b2s[t] = b2[t]; }
    __syncthreads();

    int node = blockIdx.x * 128 + t;
    if (node >= N_NODES) return;

    // load z row (64 floats) into registers
    float zf[64];
    const float4* z4 = (const float4*)(zin + node * 64);
    #pragma unroll
    for (int i = 0; i < 16; i++) {
        float4 v = z4[i];
        zf[4 * i + 0] = v.x; zf[4 * i + 1] = v.y;
        zf[4 * i + 2] = v.z; zf[4 * i + 3] = v.w;
    }

    // ---- layer 1: a = relu(z @ w1 + b1) ----
    unsigned long long acc[32];
    {
        const unsigned long long* bp = (const unsigned long long*)b1s;
        #pragma unroll
        for (int j = 0; j < 32; j++) acc[j] = bp[j];
        #pragma unroll
        for (int k = 0; k < 64; k++) {
            unsigned long long zz = f32x2_dup(zf[k]);
            const unsigned long long* wr = (const unsigned long long*)(w1s + (k << 6));
            #pragma unroll
            for (int j = 0; j < 32; j++) f32x2_fma(acc[j], zz, wr[j]);
        }
    }
    float tt[64];
    #pragma unroll
    for (int j = 0; j < 32; j++) {
        float2 p = f32x2_unpack(acc[j]);
        tt[2 * j + 0] = fmaxf(p.x, 0.f);
        tt[2 * j + 1] = fmaxf(p.y, 0.f);
    }

    // ---- layer 2: c = a @ w2 + b2 ----
    {
        const unsigned long long* bp = (const unsigned long long*)b2s;
        #pragma unroll
        for (int j = 0; j < 32; j++) acc[j] = bp[j];
        #pragma unroll
        for (int k = 0; k < 64; k++) {
            unsigned long long zz = f32x2_dup(tt[k]);
            const unsigned long long* wr = (const unsigned long long*)(w2s + (k << 6));
            #pragma unroll
            for (int j = 0; j < 32; j++) f32x2_fma(acc[j], zz, wr[j]);
        }
    }

    float4* h4 = (float4*)(hout + node * 64);
    #pragma unroll
    for (int j = 0; j < 16; j++) {
        float2 p0 = f32x2_unpack(acc[2 * j + 0]);
        float2 p1 = f32x2_unpack(acc[2 * j + 1]);
        if (RELU_OUT) {
            p0.x = fmaxf(p0.x, 0.f); p0.y = fmaxf(p0.y, 0.f);
            p1.x = fmaxf(p1.x, 0.f); p1.y = fmaxf(p1.y, 0.f);
        }
        h4[j] = make_float4(p0.x, p0.y, p1.x, p1.y);
    }
}

// ---------------- graph segment boundaries (batch is sorted) ----------------
__global__ void k_gb(const void* __restrict__ batch) {
    int g = blockIdx.x * blockDim.x + threadIdx.x;
    if (g > G) return;
    int lo = 0, hi = N_NODES;
    while (lo < hi) {
        int mid = (lo + hi) >> 1;
        int bv = load_idx(batch, mid);
        if (bv < g) lo = mid + 1; else hi = mid;
    }
    g_gb[g] = lo;
}

// ---------------- pooling: per-graph sum & max over HID dims ----------------
__global__ void __launch_bounds__(256) k_pool(const float* __restrict__ h) {
    __shared__ float ssum[4][64], smax[4][64];
    int g = blockIdx.x, t = threadIdx.x;
    int col = t & 63, ch = t >> 6;
    int beg = g_gb[g], end = g_gb[g + 1];
    float s = 0.f, m = -INFINITY;
    for (int i = beg + ch; i < end; i += 4) {
        float v = h[i * 64 + col];
        s += v; m = fmaxf(m, v);
    }
    ssum[ch][col] = s; smax[ch][col] = m;
    __syncthreads();
    if (t < 64) {
        float S = ssum[0][t] + ssum[1][t] + ssum[2][t] + ssum[3][t];
        float M = fmaxf(fmaxf(smax[0][t], smax[1][t]), fmaxf(smax[2][t], smax[3][t]));
        g_pool[g * 128 + t]      = S;
        g_pool[g * 128 + 64 + t] = M;
    }
}

// ---------------- head MLP: 128 -> 128 -> 64 -> 32 -> 16 -> 1, SiLU ----------------
__device__ __forceinline__ float silu(float x) { return x / (1.f + expf(-x)); }

__global__ void __launch_bounds__(128) k_head(float* __restrict__ out,
        const float* __restrict__ w0, const float* __restrict__ b0,
        const float* __restrict__ w1, const float* __restrict__ b1,
        const float* __restrict__ w2, const float* __restrict__ b2,
        const float* __restrict__ w3, const float* __restrict__ b3,
        const float* __restrict__ w4, const float* __restrict__ b4) {
    __shared__ float bufA[128], bufB[128];
    int g = blockIdx.x, t = threadIdx.x;
    bufA[t] = g_pool[g * 128 + t];
    __syncthreads();
    // layer 0: 128 -> 128
    {
        float a = b0[t];
        #pragma unroll 8
        for (int k = 0; k < 128; k++) a = fmaf(bufA[k], w0[k * 128 + t], a);
        bufB[t] = silu(a);
    }
    __syncthreads();
    // layer 1: 128 -> 64
    if (t < 64) {
        float a = b1[t];
        #pragma unroll 8
        for (int k = 0; k < 128; k++) a = fmaf(bufB[k], w1[k * 64 + t], a);
        bufA[t] = silu(a);
    }
    __syncthreads();
    // layer 2: 64 -> 32
    if (t < 32) {
        float a = b2[t];
        #pragma unroll 8
        for (int k = 0; k < 64; k++) a = fmaf(bufA[k], w2[k * 32 + t], a);
        bufB[t] = silu(a);
    }
    __syncthreads();
    // layer 3: 32 -> 16
    if (t < 16) {
        float a = b3[t];
        #pragma unroll
        for (int k = 0; k < 32; k++) a = fmaf(bufB[k], w3[k * 16 + t], a);
        bufA[t] = silu(a);
    }
    __syncthreads();
    // layer 4: 16 -> 1
    if (t == 0) {
        float a = b4[0];
        #pragma unroll
        for (int k = 0; k < 16; k++) a = fmaf(bufA[k], w4[k], a);
        out[g] = a;
    }
}

// ---------------- launch ----------------
extern "C" void kernel_launch(void* const* d_in, const int* in_sizes, int n_in,
                              void* d_out, int out_size) {
    const float* x     = (const float*)d_in[0];
    const void*  eidx  = d_in[1];
    const void*  batch = d_in[2];
    const float* c1w1 = (const float*)d_in[3];
    const float* c1b1 = (const float*)d_in[4];
    const float* c1w2 = (const float*)d_in[5];
    const float* c1b2 = (const float*)d_in[6];
    const float* c2w1 = (const float*)d_in[7];
    const float* c2b1 = (const float*)d_in[8];
    const float* c2w2 = (const float*)d_in[9];
    const float* c2b2 = (const float*)d_in[10];
    const float* hw0 = (const float*)d_in[11];
    const float* hb0 = (const float*)d_in[12];
    const float* hw1 = (const float*)d_in[13];
    const float* hb1 = (const float*)d_in[14];
    const float* hw2 = (const float*)d_in[15];
    const float* hb2 = (const float*)d_in[16];
    const float* hw3 = (const float*)d_in[17];
    const float* hb3 = (const float*)d_in[18];
    const float* hw4 = (const float*)d_in[19];
    const float* hb4 = (const float*)d_in[20];
    float* out = (float*)d_out;

    void *pz, *ph;
    cudaGetSymbolAddress(&pz, g_z);
    cudaGetSymbolAddress(&ph, g_h);
    float* zbuf = (float*)pz;
    float* hbuf = (float*)ph;

    const int NB = (N_NODES + 1023) / 1024;   // 196

    // dtype detection, then CSR build
    k_detect<<<1, 32>>>((const int*)eidx);
    k_zero_cnt<<<(N_NODES + 255) / 256, 256>>>();
    k_count<<<(N_EDGES + 255) / 256, 256>>>(eidx);
    k_scanA<<<NB, 1024>>>();
    k_scanB<<<1, 256>>>(NB);
    k_scanC<<<(N_NODES + 255) / 256, 256>>>();
    k_scatter<<<(N_EDGES + 255) / 256, 256>>>(eidx);

    // graph boundaries (independent of convs)
    k_gb<<<1, 256>>>(batch);

    const int aggBlocks = (N_NODES * 32 + 255) / 256;
    const int mlpBlocks = (N_NODES + 127) / 128;   // 1563

    // conv1 (+ inter-layer relu fused)
    k_agg<<<aggBlocks, 256>>>(x, zbuf);
    k_mlp<true><<<mlpBlocks, 128>>>(zbuf, hbuf, c1w1, c1b1, c1w2, c1b2);
    // conv2 (no trailing relu)
    k_agg<<<aggBlocks, 256>>>(hbuf, zbuf);
    k_mlp<false><<<mlpBlocks, 128>>>(zbuf, hbuf, c2w1, c2b1, c2w2, c2b2);

    // pooling + head
    k_pool<<<G, 256>>>(hbuf);
    k_head<<<G, 128>>>(out, hw0, hb0, hw1, hb1, hw2, hb2, hw3, hb3, hw4, hb4);
}